// round 3
// baseline (speedup 1.0000x reference)
#include <cuda_runtime.h>
#include <cstdint>
#include <cstddef>

// x [A=512, T=128, I=768]; 2-layer BiLSTM over A within T chunks, state carried
// across chunks -> per layer 2 chains (fwd/bwd) x 65536 sequential steps.
#define S_TOTAL 65536
#define CSZ 8            // CTAs per chain (one cluster); each owns 32 h-elements

// ---- static device scratch ----
__device__ float XGF[67108864];   // 65536 x 1024  fwd input contribution
__device__ float XGB[67108864];   // 65536 x 1024  bwd
__device__ float YBUF[33554432];  // 65536 x 512   layer-0 outputs [h_f | h_b]
__device__ float ZBUF[262144];    // 512 x 512     last-chunk layer-1 outputs

__device__ __forceinline__ float sigm(float x)  { return 1.f / (1.f + __expf(-x)); }
__device__ __forceinline__ float tanhx(float x) { return 1.f - 2.f / (1.f + __expf(2.f * x)); }

__device__ __forceinline__ uint32_t smem_u32(const void* p) {
    uint32_t a;
    asm("{ .reg .u64 t; cvta.to.shared.u64 t, %1; cvt.u32.u64 %0, t; }" : "=r"(a) : "l"(p));
    return a;
}
__device__ __forceinline__ void mbar_init(uint32_t addr, uint32_t cnt) {
    asm volatile("mbarrier.init.shared.b64 [%0], %1;" :: "r"(addr), "r"(cnt) : "memory");
}
__device__ __forceinline__ void mbar_wait(uint32_t addr, uint32_t parity) {
    asm volatile(
        "{\n\t.reg .pred P;\n"
        "WL_%=:\n\t"
        "mbarrier.try_wait.parity.acquire.cluster.shared::cta.b64 P, [%0], %1, 0x989680;\n\t"
        "@P bra WD_%=;\n\t"
        "bra WL_%=;\n"
        "WD_%=:\n\t}"
        :: "r"(addr), "r"(parity) : "memory");
}
__device__ __forceinline__ void st_remote_v4(uint32_t laddr, uint32_t rank,
                                             float v0, float v1, float v2, float v3) {
    asm volatile(
        "{ .reg .b32 ra;\n\t"
        "mapa.shared::cluster.u32 ra, %0, %1;\n\t"
        "st.shared::cluster.v4.f32 [ra], {%2, %3, %4, %5}; }"
        :: "r"(laddr), "r"(rank), "f"(v0), "f"(v1), "f"(v2), "f"(v3) : "memory");
}
__device__ __forceinline__ void arrive_remote(uint32_t lbar, uint32_t rank) {
    asm volatile(
        "{ .reg .b32 ra;\n\t"
        "mapa.shared::cluster.u32 ra, %0, %1;\n\t"
        "mbarrier.arrive.release.cluster.shared::cluster.b64 _, [ra]; }"
        :: "r"(lbar), "r"(rank) : "memory");
}
__device__ __forceinline__ void cluster_sync_() {
    asm volatile("barrier.cluster.arrive.aligned;" ::: "memory");
    asm volatile("barrier.cluster.wait.aligned;" ::: "memory");
}
__device__ __forceinline__ void ffma2(unsigned long long& acc, unsigned long long w,
                                      unsigned long long h) {
    asm("fma.rn.f32x2 %0, %1, %2, %0;" : "+l"(acc) : "l"(w), "l"(h));
}

// ============================================================================
// GEMM: C[65536][1024] = A @ W^T + bias, both directions via blockIdx.z.
// mode 0: row r -> x at ((r&511)*128 + (r>>9))*768 ; mode 1: row r -> YBUF+r*512
// ============================================================================
#define BM 128
#define BN 64
#define BK 16

__global__ void __launch_bounds__(256) gemm_xg(
    const float* __restrict__ A, int mode, int K,
    const float* __restrict__ Wf, const float* __restrict__ Wb,
    const float* __restrict__ bf, const float* __restrict__ bb)
{
    const float* W    = blockIdx.z ? Wb : Wf;
    const float* bias = blockIdx.z ? bb : bf;
    float*       C    = blockIdx.z ? XGB : XGF;
    const float* Ab   = mode ? (const float*)YBUF : A;

    __shared__ __align__(16) float As[BK][BM + 4];
    __shared__ __align__(16) float Bs[BK][BN + 4];

    int tid = threadIdx.x;
    int m0 = blockIdx.y * BM;
    int n0 = blockIdx.x * BN;

    int r0 = m0 + (tid >> 2);
    int r1 = r0 + 64;
    const float* arow0 = Ab + (mode ? (size_t)r0 * 512
                                    : ((size_t)(r0 & 511) * 128 + (size_t)(r0 >> 9)) * 768);
    const float* arow1 = Ab + (mode ? (size_t)r1 * 512
                                    : ((size_t)(r1 & 511) * 128 + (size_t)(r1 >> 9)) * 768);
    const float* brow  = W + (size_t)(n0 + (tid >> 2)) * K;
    int akq = (tid & 3) * 4;
    int ty = tid >> 4;
    int tx = tid & 15;

    float acc[8][4];
#pragma unroll
    for (int i = 0; i < 8; i++)
#pragma unroll
        for (int j = 0; j < 4; j++) acc[i][j] = 0.f;

    for (int k0 = 0; k0 < K; k0 += BK) {
        float4 a0 = *(const float4*)(arow0 + k0 + akq);
        float4 a1 = *(const float4*)(arow1 + k0 + akq);
        float4 b0 = *(const float4*)(brow + k0 + akq);
        __syncthreads();
        int rr = tid >> 2;
        As[akq + 0][rr] = a0.x; As[akq + 1][rr] = a0.y;
        As[akq + 2][rr] = a0.z; As[akq + 3][rr] = a0.w;
        As[akq + 0][rr + 64] = a1.x; As[akq + 1][rr + 64] = a1.y;
        As[akq + 2][rr + 64] = a1.z; As[akq + 3][rr + 64] = a1.w;
        Bs[akq + 0][rr] = b0.x; Bs[akq + 1][rr] = b0.y;
        Bs[akq + 2][rr] = b0.z; Bs[akq + 3][rr] = b0.w;
        __syncthreads();
#pragma unroll
        for (int k = 0; k < BK; k++) {
            float4 av0 = *(const float4*)&As[k][ty * 8];
            float4 av1 = *(const float4*)&As[k][ty * 8 + 4];
            float4 bv  = *(const float4*)&Bs[k][tx * 4];
            float am[8] = {av0.x, av0.y, av0.z, av0.w, av1.x, av1.y, av1.z, av1.w};
            float bn[4] = {bv.x, bv.y, bv.z, bv.w};
#pragma unroll
            for (int i = 0; i < 8; i++)
#pragma unroll
                for (int j = 0; j < 4; j++)
                    acc[i][j] = fmaf(am[i], bn[j], acc[i][j]);
        }
    }

    float4 bias4 = *(const float4*)(bias + n0 + tx * 4);
#pragma unroll
    for (int i = 0; i < 8; i++) {
        size_t r = (size_t)(m0 + ty * 8 + i);
        float4 o;
        o.x = acc[i][0] + bias4.x; o.y = acc[i][1] + bias4.y;
        o.z = acc[i][2] + bias4.z; o.w = acc[i][3] + bias4.w;
        *(float4*)(C + r * 1024 + n0 + tx * 4) = o;
    }
}

// ============================================================================
// Recurrent kernel: grid = 16 CTAs = 2 chains x cluster-of-8, 256 thr each.
// CTA crank owns h elements [crank*32, crank*32+32) -> 128 gate rows.
// Thread (e = tid>>3, kc = tid&7): partial dots for 4 gates of element e over
// k-chunk [kc*32, kc*32+32). shfl-reduce over kc; gates on kc==0 lanes.
// h broadcast all-to-all via DSMEM (st.shared::cluster.v4) + mbarrier arrives.
// fwd row n = s ; bwd row n = (s|511) - (s&511).
// ============================================================================
__global__ void __launch_bounds__(256, 1) __cluster_dims__(8, 1, 1)
lstm_kernel(const float* __restrict__ whhf, const float* __restrict__ whhb, int layer)
{
    int chain = blockIdx.x >> 3;
    int crank = blockIdx.x & 7;
    const float* xg  = chain ? XGB : XGF;
    const float* whh = chain ? whhb : whhf;

    __shared__ __align__(16) float hs[2][8][36];        // padded, conflict-free
    __shared__ __align__(8) unsigned long long mbars[2];

    int tid = threadIdx.x;
    int kc = tid & 7;
    int e  = tid >> 3;              // 0..31
    int hidx = crank * 32 + e;      // global h element
    int grow[4];
#pragma unroll
    for (int g = 0; g < 4; g++) grow[g] = g * 256 + hidx;

    uint32_t hs_u32   = smem_u32(&hs[0][0][0]);
    uint32_t mbar_u32 = smem_u32(&mbars[0]);

    if (tid == 0) { mbar_init(mbar_u32, 64); mbar_init(mbar_u32 + 8, 64); }

    // recurrent weights: 128 floats/thread as 64 packed f32x2 in registers
    unsigned long long w2[4][16];
#pragma unroll
    for (int g = 0; g < 4; g++) {
        const ulonglong2* wp = (const ulonglong2*)(whh + (size_t)grow[g] * 256 + kc * 32);
#pragma unroll
        for (int j = 0; j < 8; j++) {
            ulonglong2 v = wp[j];
            w2[g][2 * j] = v.x; w2[g][2 * j + 1] = v.y;
        }
    }

    __syncthreads();      // mbar init visible CTA-wide
    cluster_sync_();      // all CTAs' mbars initialized before any remote arrive

    float xgv[4] = {0, 0, 0, 0}, nxg[4] = {0, 0, 0, 0};
    if (kc == 0) {
        int n0 = chain ? 511 : 0;
#pragma unroll
        for (int g = 0; g < 4; g++) xgv[g] = __ldg(xg + (size_t)n0 * 1024 + grow[g]);
    }

    float c = 0.f;
    int lane = tid & 31;
    int wrp = tid >> 5;

    for (int s = 0; s < S_TOTAL; s++) {
        int ps = (s - 1) & 1;
        if (s > 0) mbar_wait(mbar_u32 + ps * 8, ((s - 1) >> 1) & 1);

        // prefetch next xg (hidden behind FMA)
        if (kc == 0 && s + 1 < S_TOTAL) {
            int sn = s + 1;
            int n = chain ? ((sn | 511) - (sn & 511)) : sn;
#pragma unroll
            for (int g = 0; g < 4; g++) nxg[g] = __ldg(xg + (size_t)n * 1024 + grow[g]);
        }

        unsigned long long a2[4] = {0ull, 0ull, 0ull, 0ull};
        if (s > 0) {
            const ulonglong2* hp = (const ulonglong2*)&hs[ps][kc][0];
#pragma unroll
            for (int j = 0; j < 8; j++) {
                ulonglong2 hv = hp[j];
#pragma unroll
                for (int g = 0; g < 4; g++) {
                    ffma2(a2[g], w2[g][2 * j],     hv.x);
                    ffma2(a2[g], w2[g][2 * j + 1], hv.y);
                }
            }
        }
        float a[4];
#pragma unroll
        for (int g = 0; g < 4; g++)
            a[g] = __uint_as_float((unsigned)(a2[g] & 0xffffffffull)) +
                   __uint_as_float((unsigned)(a2[g] >> 32));
#pragma unroll
        for (int d = 1; d < 8; d <<= 1) {
#pragma unroll
            for (int g = 0; g < 4; g++)
                a[g] += __shfl_xor_sync(0xffffffffu, a[g], d);
        }

        float h = 0.f;
        if (kc == 0) {
            float gi = a[0] + xgv[0], gf = a[1] + xgv[1];
            float gg = a[2] + xgv[2], go = a[3] + xgv[3];
            c = sigm(gf) * c + sigm(gi) * tanhx(gg);
            h = sigm(go) * tanhx(c);
            if (layer == 0) {
                int n = chain ? ((s | 511) - (s & 511)) : s;
                __stcg(&YBUF[(size_t)n * 512 + chain * 256 + hidx], h);
            } else if ((s >> 9) == 127) {
                int aa = chain ? (511 - (s & 511)) : (s & 511);
                ZBUF[(size_t)aa * 512 + chain * 256 + hidx] = h;
            }
#pragma unroll
            for (int g = 0; g < 4; g++) xgv[g] = nxg[g];
        }

        if (s < S_TOTAL - 1) {
            // gather warp's 4 h values (lanes 0,8,16,24) into lane 0 and publish
            float v0 = __shfl_sync(0xffffffffu, h, 0);
            float v1 = __shfl_sync(0xffffffffu, h, 8);
            float v2 = __shfl_sync(0xffffffffu, h, 16);
            float v3 = __shfl_sync(0xffffffffu, h, 24);
            if (lane == 0) {
                int ns = s & 1;
                uint32_t laddr = hs_u32 + (uint32_t)(ns * 288 + crank * 36 + wrp * 4) * 4u;
                uint32_t lbar  = mbar_u32 + ns * 8;
#pragma unroll
                for (int p = 0; p < CSZ; p++) st_remote_v4(laddr, p, v0, v1, v2, v3);
#pragma unroll
                for (int p = 0; p < CSZ; p++) arrive_remote(lbar, p);
            }
        }
    }
    cluster_sync_();
}

// ============================================================================
// Head: out[a] = softmax( (z[a] @ w1^T + b1) @ w2^T + b2 )
// ============================================================================
__global__ void __launch_bounds__(128) head_kernel(
    const float* __restrict__ w1, const float* __restrict__ b1,
    const float* __restrict__ w2, const float* __restrict__ b2,
    float* __restrict__ out)
{
    __shared__ float zs[512];
    __shared__ float hd[128];
    __shared__ float lg[13];
    int a = blockIdx.x, tid = threadIdx.x;

    for (int i = tid; i < 512; i += 128) zs[i] = ZBUF[(size_t)a * 512 + i];
    __syncthreads();

    float acc = b1[tid];
    const float* wr = w1 + (size_t)tid * 512;
    for (int k = 0; k < 512; k += 4) {
        acc = fmaf(wr[k],     zs[k],     acc);
        acc = fmaf(wr[k + 1], zs[k + 1], acc);
        acc = fmaf(wr[k + 2], zs[k + 2], acc);
        acc = fmaf(wr[k + 3], zs[k + 3], acc);
    }
    hd[tid] = acc;
    __syncthreads();

    if (tid < 13) {
        float l = b2[tid];
        const float* w2r = w2 + (size_t)tid * 128;
        for (int k = 0; k < 128; k++) l = fmaf(w2r[k], hd[k], l);
        lg[tid] = l;
    }
    __syncthreads();

    if (tid == 0) {
        float mx = lg[0];
        for (int k = 1; k < 13; k++) mx = fmaxf(mx, lg[k]);
        float s = 0.f, ebuf[13];
        for (int k = 0; k < 13; k++) { ebuf[k] = expf(lg[k] - mx); s += ebuf[k]; }
        float inv = 1.f / s;
        for (int k = 0; k < 13; k++) out[(size_t)a * 13 + k] = ebuf[k] * inv;
    }
}

extern "C" void kernel_launch(void* const* d_in, const int* in_sizes, int n_in,
                              void* d_out, int out_size)
{
    const float* x     = (const float*)d_in[0];
    const float* wih0f = (const float*)d_in[1];
    const float* whh0f = (const float*)d_in[2];
    const float* b0f   = (const float*)d_in[3];
    const float* wih0b = (const float*)d_in[4];
    const float* whh0b = (const float*)d_in[5];
    const float* b0b   = (const float*)d_in[6];
    const float* wih1f = (const float*)d_in[7];
    const float* whh1f = (const float*)d_in[8];
    const float* b1f   = (const float*)d_in[9];
    const float* wih1b = (const float*)d_in[10];
    const float* whh1b = (const float*)d_in[11];
    const float* b1b   = (const float*)d_in[12];
    const float* w1    = (const float*)d_in[13];
    const float* bias1 = (const float*)d_in[14];
    const float* w2    = (const float*)d_in[15];
    const float* bias2 = (const float*)d_in[16];
    float* out = (float*)d_out;

    dim3 gg(1024 / BN, 65536 / BM, 2);

    gemm_xg<<<gg, 256>>>(x, 0, 768, wih0f, wih0b, b0f, b0b);
    lstm_kernel<<<16, 256>>>(whh0f, whh0b, 0);
    gemm_xg<<<gg, 256>>>(nullptr, 1, 512, wih1f, wih1b, b1f, b1b);
    lstm_kernel<<<16, 256>>>(whh1f, whh1b, 1);
    head_kernel<<<512, 128>>>(w1, bias1, w2, bias2, out);
}

// round 5
// speedup vs baseline: 2.3051x; 2.3051x over previous
#include <cuda_runtime.h>
#include <cstdint>
#include <cstddef>

// x [A=512, T=128, I=768]; 2-layer BiLSTM over A within T chunks, state carried
// across chunks -> per layer 2 chains (fwd/bwd) x 65536 sequential steps.
#define S_TOTAL 65536
#define CSZ 8            // CTAs per chain (one cluster); each owns 32 h-elements

// ---- static device scratch ----
__device__ float XGF[67108864];   // 65536 x 1024  fwd input contribution
__device__ float XGB[67108864];   // 65536 x 1024  bwd
__device__ float YBUF[33554432];  // 65536 x 512   layer-0 outputs [h_f | h_b]
__device__ float ZBUF[262144];    // 512 x 512     last-chunk layer-1 outputs

__device__ __forceinline__ float sigm(float x)  { return 1.f / (1.f + __expf(-x)); }
__device__ __forceinline__ float tanhx(float x) { return 1.f - 2.f / (1.f + __expf(2.f * x)); }

__device__ __forceinline__ uint32_t smem_u32(const void* p) {
    uint32_t a;
    asm("{ .reg .u64 t; cvta.to.shared.u64 t, %1; cvt.u32.u64 %0, t; }" : "=r"(a) : "l"(p));
    return a;
}
// remote v4 data store (weak) to peer `rank`
__device__ __forceinline__ void st_remote_v4(uint32_t laddr, uint32_t rank,
                                             float v0, float v1, float v2, float v3) {
    asm volatile(
        "{ .reg .b32 ra;\n\t"
        "mapa.shared::cluster.u32 ra, %0, %1;\n\t"
        "st.shared::cluster.v4.f32 [ra], {%2, %3, %4, %5}; }"
        :: "r"(laddr), "r"(rank), "f"(v0), "f"(v1), "f"(v2), "f"(v3) : "memory");
}
// remote release flag store to peer `rank` (orders this thread's prior stores)
__device__ __forceinline__ void st_remote_rel(uint32_t laddr, uint32_t rank, unsigned v) {
    asm volatile(
        "{ .reg .b32 ra;\n\t"
        "mapa.shared::cluster.u32 ra, %0, %1;\n\t"
        "st.release.cluster.shared::cluster.u32 [ra], %2; }"
        :: "r"(laddr), "r"(rank), "r"(v) : "memory");
}
// local acquire load (pairs with remote release)
__device__ __forceinline__ unsigned ld_acq_sh(uint32_t laddr) {
    unsigned v;
    asm volatile("ld.acquire.cluster.shared::cta.u32 %0, [%1];" : "=r"(v) : "r"(laddr) : "memory");
    return v;
}
__device__ __forceinline__ void cluster_sync_() {
    asm volatile("barrier.cluster.arrive.aligned;" ::: "memory");
    asm volatile("barrier.cluster.wait.aligned;" ::: "memory");
}
__device__ __forceinline__ void ffma2(unsigned long long& acc, unsigned long long w,
                                      unsigned long long h) {
    asm("fma.rn.f32x2 %0, %1, %2, %0;" : "+l"(acc) : "l"(w), "l"(h));
}

// ============================================================================
// GEMM: C[65536][1024] = A @ W^T + bias, both directions via blockIdx.z.
// mode 0: row r -> x at ((r&511)*128 + (r>>9))*768 ; mode 1: row r -> YBUF+r*512
// ============================================================================
#define BM 128
#define BN 64
#define BK 16

__global__ void __launch_bounds__(256) gemm_xg(
    const float* __restrict__ A, int mode, int K,
    const float* __restrict__ Wf, const float* __restrict__ Wb,
    const float* __restrict__ bf, const float* __restrict__ bb)
{
    const float* W    = blockIdx.z ? Wb : Wf;
    const float* bias = blockIdx.z ? bb : bf;
    float*       C    = blockIdx.z ? XGB : XGF;
    const float* Ab   = mode ? (const float*)YBUF : A;

    __shared__ __align__(16) float As[BK][BM + 4];
    __shared__ __align__(16) float Bs[BK][BN + 4];

    int tid = threadIdx.x;
    int m0 = blockIdx.y * BM;
    int n0 = blockIdx.x * BN;

    int r0 = m0 + (tid >> 2);
    int r1 = r0 + 64;
    const float* arow0 = Ab + (mode ? (size_t)r0 * 512
                                    : ((size_t)(r0 & 511) * 128 + (size_t)(r0 >> 9)) * 768);
    const float* arow1 = Ab + (mode ? (size_t)r1 * 512
                                    : ((size_t)(r1 & 511) * 128 + (size_t)(r1 >> 9)) * 768);
    const float* brow  = W + (size_t)(n0 + (tid >> 2)) * K;
    int akq = (tid & 3) * 4;
    int ty = tid >> 4;
    int tx = tid & 15;

    float acc[8][4];
#pragma unroll
    for (int i = 0; i < 8; i++)
#pragma unroll
        for (int j = 0; j < 4; j++) acc[i][j] = 0.f;

    for (int k0 = 0; k0 < K; k0 += BK) {
        float4 a0 = *(const float4*)(arow0 + k0 + akq);
        float4 a1 = *(const float4*)(arow1 + k0 + akq);
        float4 b0 = *(const float4*)(brow + k0 + akq);
        __syncthreads();
        int rr = tid >> 2;
        As[akq + 0][rr] = a0.x; As[akq + 1][rr] = a0.y;
        As[akq + 2][rr] = a0.z; As[akq + 3][rr] = a0.w;
        As[akq + 0][rr + 64] = a1.x; As[akq + 1][rr + 64] = a1.y;
        As[akq + 2][rr + 64] = a1.z; As[akq + 3][rr + 64] = a1.w;
        Bs[akq + 0][rr] = b0.x; Bs[akq + 1][rr] = b0.y;
        Bs[akq + 2][rr] = b0.z; Bs[akq + 3][rr] = b0.w;
        __syncthreads();
#pragma unroll
        for (int k = 0; k < BK; k++) {
            float4 av0 = *(const float4*)&As[k][ty * 8];
            float4 av1 = *(const float4*)&As[k][ty * 8 + 4];
            float4 bv  = *(const float4*)&Bs[k][tx * 4];
            float am[8] = {av0.x, av0.y, av0.z, av0.w, av1.x, av1.y, av1.z, av1.w};
            float bn[4] = {bv.x, bv.y, bv.z, bv.w};
#pragma unroll
            for (int i = 0; i < 8; i++)
#pragma unroll
                for (int j = 0; j < 4; j++)
                    acc[i][j] = fmaf(am[i], bn[j], acc[i][j]);
        }
    }

    float4 bias4 = *(const float4*)(bias + n0 + tx * 4);
#pragma unroll
    for (int i = 0; i < 8; i++) {
        size_t r = (size_t)(m0 + ty * 8 + i);
        float4 o;
        o.x = acc[i][0] + bias4.x; o.y = acc[i][1] + bias4.y;
        o.z = acc[i][2] + bias4.z; o.w = acc[i][3] + bias4.w;
        *(float4*)(C + r * 1024 + n0 + tx * 4) = o;
    }
}

// ============================================================================
// Recurrent kernel: grid = 16 CTAs = 2 chains x cluster-of-8, 256 thr each.
// CTA crank owns h elements [crank*32, crank*32+32) -> 128 gate rows.
// Thread (e = tid>>3, kc = tid&7): partial dots for 4 gates of element e over
// k-chunk [kc*32, kc*32+32); shfl-reduce over kc; gates on kc==0 lanes.
// Broadcast: warp0 lanes 0..7 each own one peer; per-lane 8 st.v4 + 1 release
// flag. Consumers poll 8 LOCAL flags via ld.acquire. No mbarriers, no atomics.
// fwd row n = s ; bwd row n = (s|511) - (s&511).
// ============================================================================
__global__ void __launch_bounds__(256, 1) __cluster_dims__(8, 1, 1)
lstm_kernel(const float* __restrict__ whhf, const float* __restrict__ whhb, int layer)
{
    int chain = blockIdx.x >> 3;
    int crank = blockIdx.x & 7;
    const float* xg  = chain ? XGB : XGF;
    const float* whh = chain ? whhb : whhf;

    __shared__ __align__(16) float hs[2][8][36];   // [slot][rank][32+pad]
    __shared__ __align__(16) float h_stage[32];    // this CTA's h slice
    __shared__ __align__(16) unsigned flags[8];    // flags[q]: peer q's step count

    int tid = threadIdx.x;
    int kc = tid & 7;
    int e  = tid >> 3;              // 0..31
    int lane = tid & 31;
    int wrp  = tid >> 5;
    int hidx = crank * 32 + e;
    int grow[4];
#pragma unroll
    for (int g = 0; g < 4; g++) grow[g] = g * 256 + hidx;

    uint32_t hs_u32   = smem_u32(&hs[0][0][0]);
    uint32_t st_u32   = smem_u32(&h_stage[0]);
    uint32_t flag_u32 = smem_u32(&flags[0]);

    if (tid < 8) flags[tid] = 0u;

    // recurrent weights: 128 floats/thread as 64 packed f32x2 in registers
    unsigned long long w2[4][16];
#pragma unroll
    for (int g = 0; g < 4; g++) {
        const ulonglong2* wp = (const ulonglong2*)(whh + (size_t)grow[g] * 256 + kc * 32);
#pragma unroll
        for (int j = 0; j < 8; j++) {
            ulonglong2 v = wp[j];
            w2[g][2 * j] = v.x; w2[g][2 * j + 1] = v.y;
        }
    }

    __syncthreads();
    cluster_sync_();   // flags zeroed cluster-wide before any publish

    float xgv[4] = {0, 0, 0, 0}, nxg[4] = {0, 0, 0, 0};
    if (kc == 0) {
        int n0 = chain ? 511 : 0;
#pragma unroll
        for (int g = 0; g < 4; g++) xgv[g] = __ldg(xg + (size_t)n0 * 1024 + grow[g]);
    }

    float c = 0.f;

    for (int s = 0; s < S_TOTAL; s++) {
        // ---- wait: all 8 peers published h_{s-1} (flag >= s) ----
        if (s > 0) {
            unsigned tgt = (unsigned)s;
            bool done;
            do {
                unsigned v = 0xffffffffu;
                if (lane < 8) v = ld_acq_sh(flag_u32 + lane * 4);
                done = __all_sync(0xffffffffu, v >= tgt);
            } while (!done);
        }

        // prefetch next xg (off critical path)
        if (kc == 0 && s + 1 < S_TOTAL) {
            int sn = s + 1;
            int n = chain ? ((sn | 511) - (sn & 511)) : sn;
#pragma unroll
            for (int g = 0; g < 4; g++) nxg[g] = __ldg(xg + (size_t)n * 1024 + grow[g]);
        }

        // ---- partial dot products over this thread's k-chunk ----
        unsigned long long a2[4] = {0ull, 0ull, 0ull, 0ull};
        if (s > 0) {
            int ps = (s - 1) & 1;
            const ulonglong2* hp = (const ulonglong2*)&hs[ps][kc][0];
#pragma unroll
            for (int j = 0; j < 8; j++) {
                ulonglong2 hv = hp[j];
#pragma unroll
                for (int g = 0; g < 4; g++) {
                    ffma2(a2[g], w2[g][2 * j],     hv.x);
                    ffma2(a2[g], w2[g][2 * j + 1], hv.y);
                }
            }
        }
        float a[4];
#pragma unroll
        for (int g = 0; g < 4; g++)
            a[g] = __uint_as_float((unsigned)(a2[g] & 0xffffffffull)) +
                   __uint_as_float((unsigned)(a2[g] >> 32));
#pragma unroll
        for (int d = 1; d < 8; d <<= 1) {
#pragma unroll
            for (int g = 0; g < 4; g++)
                a[g] += __shfl_xor_sync(0xffffffffu, a[g], d);
        }

        // ---- gates + state update on kc==0 lanes ----
        if (kc == 0) {
            float gi = a[0] + xgv[0], gf = a[1] + xgv[1];
            float gg = a[2] + xgv[2], go = a[3] + xgv[3];
            c = sigm(gf) * c + sigm(gi) * tanhx(gg);
            float h = sigm(go) * tanhx(c);
            h_stage[e] = h;
            if (layer == 0) {
                int n = chain ? ((s | 511) - (s & 511)) : s;
                __stcg(&YBUF[(size_t)n * 512 + chain * 256 + hidx], h);
            } else if ((s >> 9) == 127) {
                int aa = chain ? (511 - (s & 511)) : (s & 511);
                ZBUF[(size_t)aa * 512 + chain * 256 + hidx] = h;
            }
#pragma unroll
            for (int g = 0; g < 4; g++) xgv[g] = nxg[g];
        }

        if (s < S_TOTAL - 1) {
            __syncthreads();   // h_stage visible to warp 0
            if (wrp == 0 && lane < 8) {
                int slot = s & 1;
                uint32_t dst = hs_u32 + (uint32_t)(slot * 288 + crank * 36) * 4u;
#pragma unroll
                for (int j = 0; j < 8; j++) {
                    float4 v;
                    asm volatile("ld.shared.v4.f32 {%0,%1,%2,%3}, [%4];"
                                 : "=f"(v.x), "=f"(v.y), "=f"(v.z), "=f"(v.w)
                                 : "r"(st_u32 + j * 16));
                    st_remote_v4(dst + j * 16, (uint32_t)lane, v.x, v.y, v.z, v.w);
                }
                st_remote_rel(flag_u32 + crank * 4, (uint32_t)lane, (unsigned)(s + 1));
            }
        }
    }
    cluster_sync_();
}

// ============================================================================
// Head: out[a] = softmax( (z[a] @ w1^T + b1) @ w2^T + b2 )
// ============================================================================
__global__ void __launch_bounds__(128) head_kernel(
    const float* __restrict__ w1, const float* __restrict__ b1,
    const float* __restrict__ w2, const float* __restrict__ b2,
    float* __restrict__ out)
{
    __shared__ float zs[512];
    __shared__ float hd[128];
    __shared__ float lg[13];
    int a = blockIdx.x, tid = threadIdx.x;

    for (int i = tid; i < 512; i += 128) zs[i] = ZBUF[(size_t)a * 512 + i];
    __syncthreads();

    float acc = b1[tid];
    const float* wr = w1 + (size_t)tid * 512;
    for (int k = 0; k < 512; k += 4) {
        acc = fmaf(wr[k],     zs[k],     acc);
        acc = fmaf(wr[k + 1], zs[k + 1], acc);
        acc = fmaf(wr[k + 2], zs[k + 2], acc);
        acc = fmaf(wr[k + 3], zs[k + 3], acc);
    }
    hd[tid] = acc;
    __syncthreads();

    if (tid < 13) {
        float l = b2[tid];
        const float* w2r = w2 + (size_t)tid * 128;
        for (int k = 0; k < 128; k++) l = fmaf(w2r[k], hd[k], l);
        lg[tid] = l;
    }
    __syncthreads();

    if (tid == 0) {
        float mx = lg[0];
        for (int k = 1; k < 13; k++) mx = fmaxf(mx, lg[k]);
        float s = 0.f, ebuf[13];
        for (int k = 0; k < 13; k++) { ebuf[k] = expf(lg[k] - mx); s += ebuf[k]; }
        float inv = 1.f / s;
        for (int k = 0; k < 13; k++) out[(size_t)a * 13 + k] = ebuf[k] * inv;
    }
}

extern "C" void kernel_launch(void* const* d_in, const int* in_sizes, int n_in,
                              void* d_out, int out_size)
{
    const float* x     = (const float*)d_in[0];
    const float* wih0f = (const float*)d_in[1];
    const float* whh0f = (const float*)d_in[2];
    const float* b0f   = (const float*)d_in[3];
    const float* wih0b = (const float*)d_in[4];
    const float* whh0b = (const float*)d_in[5];
    const float* b0b   = (const float*)d_in[6];
    const float* wih1f = (const float*)d_in[7];
    const float* whh1f = (const float*)d_in[8];
    const float* b1f   = (const float*)d_in[9];
    const float* wih1b = (const float*)d_in[10];
    const float* whh1b = (const float*)d_in[11];
    const float* b1b   = (const float*)d_in[12];
    const float* w1    = (const float*)d_in[13];
    const float* bias1 = (const float*)d_in[14];
    const float* w2    = (const float*)d_in[15];
    const float* bias2 = (const float*)d_in[16];
    float* out = (float*)d_out;

    dim3 gg(1024 / BN, 65536 / BM, 2);

    gemm_xg<<<gg, 256>>>(x, 0, 768, wih0f, wih0b, b0f, b0b);
    lstm_kernel<<<16, 256>>>(whh0f, whh0b, 0);
    gemm_xg<<<gg, 256>>>(nullptr, 1, 512, wih1f, wih1b, b1f, b1b);
    lstm_kernel<<<16, 256>>>(whh1f, whh1b, 1);
    head_kernel<<<512, 128>>>(w1, bias1, w2, bias2, out);
}